// round 14
// baseline (speedup 1.0000x reference)
#include <cuda_runtime.h>
#include <cstdint>
#include <cuda_fp16.h>

#define B_    128
#define H_    1024
#define T_    256
#define D_    128
#define PRED_ 96
#define G4    4096

// ---- smem geometry (all word = uint32 = half2 units) ----
#define PA2       20                    // A row pitch: 16 data words (32 k fp16) + 4 pad
#define AS_WORDS  (128 * PA2)           // 2560 words per A buffer
#define W_OFF     (4 * AS_WORDS)        // A region: [2 groups][2 bufs]
#define PKP1      1028                  // W col pitch (kp units), 1028 % 32 == 4
#define PKP0      580                   // 580 % 32 == 4
#define RED_WORDS (256 * 16)            // dedicated reduction buffer (16 KB)
#define SMEM_WORDS_MAX (W_OFF + 32 * PKP1 + RED_WORDS)   // 47232 words
#define SMEM_BYTES_MAX (SMEM_WORDS_MAX * 4)              // 188928 B

// -------- scratch (static __device__; no allocation allowed) --------
__device__ alignas(256) __half g_Xseq16[(size_t)T_ * B_ * D_];   // [t][b][d]
__device__ alignas(256) __half g_HS016[(size_t)T_ * B_ * H_];    // [t][b][h]
__device__ alignas(256) __half g_h16A[B_ * H_];
__device__ alignas(256) __half g_h16B[B_ * H_];
__device__ alignas(256) float  g_c[B_ * H_];
__device__ unsigned g_barcnt;

__device__ __forceinline__ uint32_t f2h2(float a, float b) {
    __half2 h = __floats2half2_rn(a, b);      // .x = a (low 16) = even k
    return *(uint32_t*)&h;
}
__device__ __forceinline__ float sigf(float x) { return 1.f / (1.f + __expf(-x)); }
__device__ __forceinline__ void barg(int id) {
    asm volatile("bar.sync %0, %1;" :: "r"(id), "r"(256) : "memory");
}
__device__ __forceinline__ uint4 ldcg4u(const uint32_t* p) {
    uint4 v;
    asm volatile("ld.global.cg.v4.u32 {%0,%1,%2,%3}, [%4];"
                 : "=r"(v.x), "=r"(v.y), "=r"(v.z), "=r"(v.w) : "l"(p));
    return v;
}

// -------- transpose x[b][d][t] -> Xseq16[t][b][d] (fp16) --------
__global__ void k_transpose(const float* __restrict__ x) {
    __shared__ float tile[32][33];
    int b  = blockIdx.z;
    int d0 = blockIdx.x * 32, t0 = blockIdx.y * 32;
    int tx = threadIdx.x, ty = threadIdx.y;
#pragma unroll
    for (int i = 0; i < 32; i += 8)
        tile[ty + i][tx] = x[((size_t)b * D_ + d0 + ty + i) * T_ + t0 + tx];
    __syncthreads();
#pragma unroll
    for (int i = 0; i < 32; i += 8)
        g_Xseq16[((size_t)(t0 + ty + i) * B_ + b) * D_ + d0 + tx] =
            __float2half_rn(tile[tx][ty + i]);
}

__global__ void k_zero() {
    int i = blockIdx.x * blockDim.x + threadIdx.x;
    if (i < B_ * H_) { g_h16A[i] = __float2half_rn(0.f); g_c[i] = 0.f; }
    if (i == 0) g_barcnt = 0u;
}

// -------- persistent per-layer LSTM kernel --------
// grid 128 CTAs (1/SM), block 512 = 2 groups x 8 warps.
// CTA j: hidden units [8j,8j+8) -> 32 gate cols. group g: K-half g.
// W resident in smem fp16 (col-major, pitch PKP). Loop over T steps with a
// global spin barrier; in layer 1, group0's K-half is entirely HS0 (static),
// so only group1 waits on the barrier — group0 races ahead.
__global__ void __launch_bounds__(512) k_layer(
    int layer, int tbase,
    const float* __restrict__ W, const float* __restrict__ bias)
{
    const int K1   = layer ? H_ : D_;
    const int Ktot = K1 + H_;
    const int PKP  = layer ? PKP1 : PKP0;

    extern __shared__ uint32_t smem[];
    uint32_t* As  = smem;                        // [group][buf][AS_WORDS]
    uint32_t* Wsm = smem + W_OFF;                // [32 cols][PKP kp]
    float*    red = (float*)(smem + W_OFF + 32 * PKP);   // dedicated

    const int tid   = threadIdx.x;
    const int group = tid >> 8;
    const int gtid  = tid & 255;
    const int warp  = gtid >> 5, lane = gtid & 31;
    const int j0 = blockIdx.x * 8;
    const int m0 = warp * 16;
    const int r = lane >> 2, q = lane & 3;

    // ---- load W slice into smem (once) ----
    {
        const int kpRows = Ktot >> 1;
        for (int idx = tid; idx < kpRows * 32; idx += 512) {
            int kp = idx >> 5, cl = idx & 31;
            int gcol = (cl >> 3) * H_ + j0 + (cl & 7);
            float w0 = W[(size_t)(2 * kp)     * G4 + gcol];
            float w1 = W[(size_t)(2 * kp + 1) * G4 + gcol];
            Wsm[cl * PKP + kp] = f2h2(w0, w1);
        }
    }
    __syncthreads();

    // prefetch mapping: 2 threads per A row, 8 half2 words each
    const int am  = gtid >> 1;            // A row 0..127
    const int akp = (gtid & 1) * 8;       // word offset in 16-word row chunk
    const int Khalf  = Ktot >> 1;
    const int kstart = group * Khalf;
    const int kend   = kstart + Khalf;
    const int barid  = 1 + group;

    for (int t = 0; t < T_; t++) {
        const int par = t & 1;
        const __half* A1    = layer ? (g_HS016 + (size_t)t * B_ * H_)
                                    : (g_Xseq16 + (size_t)t * B_ * D_);
        const __half* hprev = par ? g_h16B : g_h16A;
        __half*       hnext = par ? g_h16A : g_h16B;
        __half*       hs    = layer ? nullptr : (g_HS016 + (size_t)t * B_ * H_);

        float acc[4][4];
#pragma unroll
        for (int g = 0; g < 4; g++)
#pragma unroll
            for (int k = 0; k < 4; k++) acc[g][k] = 0.f;

        uint4 pa0, pa1;
        // ---- prefetch first chunk of this group's K-range ----
        {
            int kn = kstart;
            const __half* A; int stride, arow;
            if (kn < K1) { A = A1;    stride = K1; arow = kn; }
            else         { A = hprev; stride = H_; arow = kn - K1; }
            const uint32_t* src = (const uint32_t*)A
                + ((((size_t)am * stride + arow)) >> 1) + akp;
            pa0 = ldcg4u(src);
            pa1 = ldcg4u(src + 4);
        }

        int buf = 0;
        for (int kb = kstart; kb < kend; kb += 32, buf ^= 1) {
            // ---- store prefetched A -> smem[group][buf] ----
            {
                uint32_t* dst = As + group * (2 * AS_WORDS) + buf * AS_WORDS
                                   + am * PA2 + akp;
                *(uint4*)(dst)     = pa0;
                *(uint4*)(dst + 4) = pa1;
            }
            barg(barid);

            // ---- prefetch next chunk (overlaps MMA) ----
            if (kb + 32 < kend) {
                int kn = kb + 32;
                const __half* A; int stride, arow;
                if (kn < K1) { A = A1;    stride = K1; arow = kn; }
                else         { A = hprev; stride = H_; arow = kn - K1; }
                const uint32_t* src = (const uint32_t*)A
                    + ((((size_t)am * stride + arow)) >> 1) + akp;
                pa0 = ldcg4u(src);
                pa1 = ldcg4u(src + 4);
            }

            // ---- MMA: A from smem buf, B(W) from resident smem ----
            const uint32_t* as = As + group * (2 * AS_WORDS) + buf * AS_WORDS;
            const int kpg = kb >> 1;
#pragma unroll
            for (int ks = 0; ks < 2; ks++) {
                const int kpb = ks * 8;
                // m16n8k16 f16 A frag: a0=(r,2q) a1=(r+8,2q) a2=(r,2q+8) a3=(r+8,2q+8)
                uint32_t a0 = as[(m0 + r)     * PA2 + kpb + q];
                uint32_t a1 = as[(m0 + r + 8) * PA2 + kpb + q];
                uint32_t a2 = as[(m0 + r)     * PA2 + kpb + q + 4];
                uint32_t a3 = as[(m0 + r + 8) * PA2 + kpb + q + 4];
#pragma unroll
                for (int g = 0; g < 4; g++) {
                    const uint32_t* wr = Wsm + (g * 8 + r) * PKP + kpg + kpb;
                    uint32_t b0 = wr[q];
                    uint32_t b1 = wr[q + 4];
                    asm volatile(
                        "mma.sync.aligned.m16n8k16.row.col.f32.f16.f16.f32 "
                        "{%0,%1,%2,%3}, {%4,%5,%6,%7}, {%8,%9}, {%0,%1,%2,%3};"
                        : "+f"(acc[g][0]), "+f"(acc[g][1]),
                          "+f"(acc[g][2]), "+f"(acc[g][3])
                        : "r"(a0), "r"(a1), "r"(a2), "r"(a3), "r"(b0), "r"(b1));
                }
            }
        }

        // ---- cross-group reduction (red is dedicated memory) ----
        if (group == 1) {
#pragma unroll
            for (int g = 0; g < 4; g++)
#pragma unroll
                for (int k = 0; k < 4; k++)
                    red[gtid * 16 + g * 4 + k] = acc[g][k];
        }
        __syncthreads();
        if (group == 0) {
#pragma unroll
            for (int g = 0; g < 4; g++)
#pragma unroll
                for (int k = 0; k < 4; k++)
                    acc[g][k] += red[gtid * 16 + g * 4 + k];

            // epilogue: c0:(r,2q) c1:(r,2q+1) c2:(r+8,2q) c3:(r+8,2q+1)
#pragma unroll
            for (int reg = 0; reg < 4; reg++) {
                int b = m0 + r + ((reg & 2) ? 8 : 0);
                int u = q * 2 + (reg & 1);
                int j = j0 + u;
                float zi = acc[0][reg] + bias[j];
                float zf = acc[1][reg] + bias[H_ + j];
                float zo = acc[2][reg] + bias[2 * H_ + j];
                float zg = acc[3][reg] + bias[3 * H_ + j];
                float i_ = sigf(zi), f_ = sigf(zf), o_ = sigf(zo);
                float g_ = tanhf(zg);
                float cn = f_ * g_c[b * H_ + j] + i_ * g_;
                float hn = o_ * tanhf(cn);
                g_c[b * H_ + j]   = cn;
                __half hh = __float2half_rn(hn);
                hnext[b * H_ + j] = hh;
                if (hs) hs[b * H_ + j] = hh;
            }
        }

        // ---- global barrier: release stores, arrive; selective wait ----
        __threadfence();
        __syncthreads();                 // all CTA threads' stores fenced
        if (tid == 0) atomicAdd(&g_barcnt, 1u);
        if (t + 1 < T_) {
            unsigned target = 128u * (unsigned)(tbase + t + 1);
            if (layer == 0) {
                // both groups read h next step -> whole block waits
                if (tid == 0) {
                    while (*(volatile unsigned*)&g_barcnt < target) __nanosleep(64);
                    __threadfence();
                }
                __syncthreads();
            } else {
                // layer 1: group0's K-half is all HS0 (static) -> no wait
                if (group == 1) {
                    if (gtid == 0) {
                        while (*(volatile unsigned*)&g_barcnt < target) __nanosleep(64);
                        __threadfence();
                    }
                    barg(4);
                }
            }
        }
    }
}

// -------- final FC head: out = tanh(h @ fc_w + fc_b) --------
__global__ void k_fc(const float* __restrict__ fcw,
                     const float* __restrict__ fcb, float* __restrict__ out) {
    const __half* h = g_h16A;            // final parity = 0
    __shared__ float hsh[H_];
    int b = blockIdx.x;
    for (int i = threadIdx.x; i < H_; i += blockDim.x)
        hsh[i] = __half2float(h[b * H_ + i]);
    __syncthreads();
    for (int p = threadIdx.x; p < PRED_; p += blockDim.x) {
        float s = fcb[p];
#pragma unroll 8
        for (int k = 0; k < H_; k++) s += hsh[k] * fcw[k * PRED_ + p];
        out[b * PRED_ + p] = tanhf(s);
    }
}

__global__ void k_copy(float* __restrict__ out) {
    int i = blockIdx.x * blockDim.x + threadIdx.x;
    if (i < B_ * H_) {
        out[B_ * PRED_ + i]           = __half2float(g_h16A[i]);
        out[B_ * PRED_ + B_ * H_ + i] = g_c[i];
    }
}

extern "C" void kernel_launch(void* const* d_in, const int* in_sizes, int n_in,
                              void* d_out, int out_size) {
    const float* x   = (const float*)d_in[0];
    const float* W0  = (const float*)d_in[1];
    const float* b0  = (const float*)d_in[2];
    const float* W1  = (const float*)d_in[3];
    const float* b1  = (const float*)d_in[4];
    const float* fcw = (const float*)d_in[5];
    const float* fcb = (const float*)d_in[6];
    float* out = (float*)d_out;

    cudaFuncSetAttribute(k_layer, cudaFuncAttributeMaxDynamicSharedMemorySize,
                         SMEM_BYTES_MAX);

    dim3 tg(D_ / 32, T_ / 32, B_);
    k_transpose<<<tg, dim3(32, 8)>>>(x);
    k_zero<<<(B_ * H_ + 255) / 256, 256>>>();

    k_layer<<<128, 512, SMEM_BYTES_MAX>>>(0, 0,  W0, b0);
    k_layer<<<128, 512, SMEM_BYTES_MAX>>>(1, T_, W1, b1);

    k_fc<<<B_, 96>>>(fcw, fcb, out);
    k_copy<<<(B_ * H_ + 255) / 256, 256>>>(out);
}

// round 15
// speedup vs baseline: 1.2644x; 1.2644x over previous
#include <cuda_runtime.h>
#include <cstdint>
#include <cuda_fp16.h>

#define B_    128
#define H_    1024
#define T_    256
#define D_    128
#define PRED_ 96
#define G4    4096

// ---- smem geometry (word = uint32 = half2) ----
#define PA2       20                    // A row pitch: 16 data words + 4 pad
#define AS_WORDS  (128 * PA2)           // 2560 words per A buffer
#define NBUF      4
#define W_OFF     (2 * NBUF * AS_WORDS) // 20480 words: A[2 groups][4 bufs]
#define PKP1      1028                  // W col pitch (kp units), %32==4
#define PKP0      580                   // %32==4
#define SMEM_WORDS_MAX (W_OFF + 32 * PKP1)     // 53376 words
#define SMEM_BYTES_MAX (SMEM_WORDS_MAX * 4)    // 213504 B

// -------- scratch --------
__device__ alignas(256) __half g_Xseq16[(size_t)T_ * B_ * D_];
__device__ alignas(256) __half g_HS016[(size_t)T_ * B_ * H_];
__device__ alignas(256) __half g_h16A[B_ * H_];
__device__ alignas(256) __half g_h16B[B_ * H_];
__device__ alignas(256) float  g_c[B_ * H_];
__device__ unsigned g_flag[B_];          // per-CTA step flags

__device__ __forceinline__ uint32_t f2h2(float a, float b) {
    __half2 h = __floats2half2_rn(a, b);
    return *(uint32_t*)&h;
}
__device__ __forceinline__ float sigf(float x) { return 1.f / (1.f + __expf(-x)); }
__device__ __forceinline__ void barg(int id) {
    asm volatile("bar.sync %0, %1;" :: "r"(id), "r"(256) : "memory");
}
__device__ __forceinline__ uint4 ldcg4u(const uint32_t* p) {
    uint4 v;
    asm volatile("ld.global.cg.v4.u32 {%0,%1,%2,%3}, [%4];"
                 : "=r"(v.x), "=r"(v.y), "=r"(v.z), "=r"(v.w) : "l"(p));
    return v;
}

// -------- transpose x[b][d][t] -> Xseq16[t][b][d] --------
__global__ void k_transpose(const float* __restrict__ x) {
    __shared__ float tile[32][33];
    int b  = blockIdx.z;
    int d0 = blockIdx.x * 32, t0 = blockIdx.y * 32;
    int tx = threadIdx.x, ty = threadIdx.y;
#pragma unroll
    for (int i = 0; i < 32; i += 8)
        tile[ty + i][tx] = x[((size_t)b * D_ + d0 + ty + i) * T_ + t0 + tx];
    __syncthreads();
#pragma unroll
    for (int i = 0; i < 32; i += 8)
        g_Xseq16[((size_t)(t0 + ty + i) * B_ + b) * D_ + d0 + tx] =
            __float2half_rn(tile[tx][ty + i]);
}

__global__ void k_zero() {
    int i = blockIdx.x * blockDim.x + threadIdx.x;
    if (i < B_ * H_) { g_h16A[i] = __float2half_rn(0.f); g_c[i] = 0.f; }
    if (i < B_) g_flag[i] = 0u;
}

// -------- persistent per-layer LSTM kernel --------
// grid 128 CTAs (1/SM), block 512 = 2 groups x 8 warps.
// CTA j: hidden units [8j,8j+8) -> 32 gate cols. group g: K-half g.
// W resident in smem fp16. k-loop: 2 chunks (64 k) per barrier, 4 A-buffers,
// prefetch one pair ahead. Inter-step sync: per-CTA flag array (no atomics).
__global__ void __launch_bounds__(512) k_layer(
    int layer, int tbase,
    const float* __restrict__ W, const float* __restrict__ bias)
{
    const int K1   = layer ? H_ : D_;
    const int Ktot = K1 + H_;
    const int PKP  = layer ? PKP1 : PKP0;

    extern __shared__ uint32_t smem[];
    uint32_t* As  = smem;                        // [group][4 bufs][AS_WORDS]
    uint32_t* Wsm = smem + W_OFF;                // [32 cols][PKP kp]
    float*    red = (float*)(smem + NBUF * AS_WORDS);   // aliases group1 bufs

    const int tid   = threadIdx.x;
    const int group = tid >> 8;
    const int gtid  = tid & 255;
    const int warp  = gtid >> 5, lane = gtid & 31;
    const int j0 = blockIdx.x * 8;
    const int m0 = warp * 16;
    const int r = lane >> 2, q = lane & 3;

    // ---- load W slice into smem (once) ----
    {
        const int kpRows = Ktot >> 1;
        for (int idx = tid; idx < kpRows * 32; idx += 512) {
            int kp = idx >> 5, cl = idx & 31;
            int gcol = (cl >> 3) * H_ + j0 + (cl & 7);
            float w0 = W[(size_t)(2 * kp)     * G4 + gcol];
            float w1 = W[(size_t)(2 * kp + 1) * G4 + gcol];
            Wsm[cl * PKP + kp] = f2h2(w0, w1);
        }
    }
    __syncthreads();

    const int am  = gtid >> 1;            // A row 0..127
    const int akp = (gtid & 1) * 8;       // word offset in 16-word row chunk
    const int Khalf  = Ktot >> 1;         // 64-aligned for both layers
    const int kstart = group * Khalf;
    const int kend   = kstart + Khalf;
    const int barid  = 1 + group;
    uint32_t* AsG = As + group * (NBUF * AS_WORDS);

    for (int t = 0; t < T_; t++) {
        const int par = t & 1;
        const __half* A1    = layer ? (g_HS016 + (size_t)t * B_ * H_)
                                    : (g_Xseq16 + (size_t)t * B_ * D_);
        const __half* hprev = par ? g_h16B : g_h16A;
        __half*       hnext = par ? g_h16A : g_h16B;
        __half*       hs    = layer ? nullptr : (g_HS016 + (size_t)t * B_ * H_);

        float acc[4][4];
#pragma unroll
        for (int g = 0; g < 4; g++)
#pragma unroll
            for (int k = 0; k < 4; k++) acc[g][k] = 0.f;

        // chunk-source address helper
        auto srcp = [&](int kn) -> const uint32_t* {
            const __half* A; int stride, arow;
            if (kn < K1) { A = A1;    stride = K1; arow = kn; }
            else         { A = hprev; stride = H_; arow = kn - K1; }
            return (const uint32_t*)A + (((size_t)am * stride + arow) >> 1) + akp;
        };

        uint4 P[4];   // prefetched pair: 2 chunks x 16 words (2 uint4 each)
        {
            const uint32_t* s0 = srcp(kstart);
            const uint32_t* s1 = srcp(kstart + 32);
            P[0] = ldcg4u(s0); P[1] = ldcg4u(s0 + 4);
            P[2] = ldcg4u(s1); P[3] = ldcg4u(s1 + 4);
        }

        int buf = 0;   // 0 or 2: pair occupies bufs {buf, buf+1}
        for (int kb = kstart; kb < kend; kb += 64, buf ^= 2) {
            // ---- store prefetched pair -> bufs {buf, buf+1} ----
            {
                uint32_t* d0 = AsG + buf * AS_WORDS + am * PA2 + akp;
                *(uint4*)(d0)     = P[0];
                *(uint4*)(d0 + 4) = P[1];
                uint32_t* d1 = AsG + (buf + 1) * AS_WORDS + am * PA2 + akp;
                *(uint4*)(d1)     = P[2];
                *(uint4*)(d1 + 4) = P[3];
            }
            barg(barid);

            // ---- prefetch next pair (overlaps 2 chunks of MMA) ----
            if (kb + 64 < kend) {
                const uint32_t* s0 = srcp(kb + 64);
                const uint32_t* s1 = srcp(kb + 96);
                P[0] = ldcg4u(s0); P[1] = ldcg4u(s0 + 4);
                P[2] = ldcg4u(s1); P[3] = ldcg4u(s1 + 4);
            }

            // ---- MMA on the 2 stored chunks ----
#pragma unroll
            for (int half = 0; half < 2; half++) {
                const uint32_t* as = AsG + (buf + half) * AS_WORDS;
                const int kpg = (kb + half * 32) >> 1;
#pragma unroll
                for (int ks = 0; ks < 2; ks++) {
                    const int kpb = ks * 8;
                    uint32_t a0 = as[(m0 + r)     * PA2 + kpb + q];
                    uint32_t a1 = as[(m0 + r + 8) * PA2 + kpb + q];
                    uint32_t a2 = as[(m0 + r)     * PA2 + kpb + q + 4];
                    uint32_t a3 = as[(m0 + r + 8) * PA2 + kpb + q + 4];
#pragma unroll
                    for (int g = 0; g < 4; g++) {
                        const uint32_t* wr = Wsm + (g * 8 + r) * PKP + kpg + kpb;
                        uint32_t b0 = wr[q];
                        uint32_t b1 = wr[q + 4];
                        asm volatile(
                            "mma.sync.aligned.m16n8k16.row.col.f32.f16.f16.f32 "
                            "{%0,%1,%2,%3}, {%4,%5,%6,%7}, {%8,%9}, {%0,%1,%2,%3};"
                            : "+f"(acc[g][0]), "+f"(acc[g][1]),
                              "+f"(acc[g][2]), "+f"(acc[g][3])
                            : "r"(a0), "r"(a1), "r"(a2), "r"(a3),
                              "r"(b0), "r"(b1));
                    }
                }
            }
        }

        // ---- cross-group reduction (red aliases group1 bufs; guard) ----
        if (group == 1) {
            barg(2);   // all group-1 warps done reading group-1 bufs
#pragma unroll
            for (int g = 0; g < 4; g++)
#pragma unroll
                for (int k = 0; k < 4; k++)
                    red[gtid * 16 + g * 4 + k] = acc[g][k];
        }
        __syncthreads();
        if (group == 0) {
#pragma unroll
            for (int g = 0; g < 4; g++)
#pragma unroll
                for (int k = 0; k < 4; k++)
                    acc[g][k] += red[gtid * 16 + g * 4 + k];

            // epilogue: c0:(r,2q) c1:(r,2q+1) c2:(r+8,2q) c3:(r+8,2q+1)
#pragma unroll
            for (int reg = 0; reg < 4; reg++) {
                int b = m0 + r + ((reg & 2) ? 8 : 0);
                int u = q * 2 + (reg & 1);
                int j = j0 + u;
                float zi = acc[0][reg] + bias[j];
                float zf = acc[1][reg] + bias[H_ + j];
                float zo = acc[2][reg] + bias[2 * H_ + j];
                float zg = acc[3][reg] + bias[3 * H_ + j];
                float i_ = sigf(zi), f_ = sigf(zf), o_ = sigf(zo);
                float g_ = tanhf(zg);
                float cn = f_ * g_c[b * H_ + j] + i_ * g_;
                float hn = o_ * tanhf(cn);
                g_c[b * H_ + j]   = cn;
                __half hh = __float2half_rn(hn);
                hnext[b * H_ + j] = hh;
                if (hs) hs[b * H_ + j] = hh;
            }
        }

        // ---- global barrier via per-CTA flags ----
        __threadfence();
        __syncthreads();                 // all stores in CTA fenced
        if (tid == 0)
            *(volatile unsigned*)&g_flag[blockIdx.x] = (unsigned)(tbase + t + 1);
        if (t + 1 < T_) {
            unsigned target = (unsigned)(tbase + t + 1);
            if (tid < B_) {
                while (*(volatile unsigned*)&g_flag[tid] < target) __nanosleep(32);
                __threadfence();
            }
            __syncthreads();
        }
    }
}

// -------- final FC head --------
__global__ void k_fc(const float* __restrict__ fcw,
                     const float* __restrict__ fcb, float* __restrict__ out) {
    const __half* h = g_h16A;            // final parity = 0
    __shared__ float hsh[H_];
    int b = blockIdx.x;
    for (int i = threadIdx.x; i < H_; i += blockDim.x)
        hsh[i] = __half2float(h[b * H_ + i]);
    __syncthreads();
    for (int p = threadIdx.x; p < PRED_; p += blockDim.x) {
        float s = fcb[p];
#pragma unroll 8
        for (int k = 0; k < H_; k++) s += hsh[k] * fcw[k * PRED_ + p];
        out[b * PRED_ + p] = tanhf(s);
    }
}

__global__ void k_copy(float* __restrict__ out) {
    int i = blockIdx.x * blockDim.x + threadIdx.x;
    if (i < B_ * H_) {
        out[B_ * PRED_ + i]           = __half2float(g_h16A[i]);
        out[B_ * PRED_ + B_ * H_ + i] = g_c[i];
    }
}

extern "C" void kernel_launch(void* const* d_in, const int* in_sizes, int n_in,
                              void* d_out, int out_size) {
    const float* x   = (const float*)d_in[0];
    const float* W0  = (const float*)d_in[1];
    const float* b0  = (const float*)d_in[2];
    const float* W1  = (const float*)d_in[3];
    const float* b1  = (const float*)d_in[4];
    const float* fcw = (const float*)d_in[5];
    const float* fcb = (const float*)d_in[6];
    float* out = (float*)d_out;

    cudaFuncSetAttribute(k_layer, cudaFuncAttributeMaxDynamicSharedMemorySize,
                         SMEM_BYTES_MAX);

    dim3 tg(D_ / 32, T_ / 32, B_);
    k_transpose<<<tg, dim3(32, 8)>>>(x);
    k_zero<<<(B_ * H_ + 255) / 256, 256>>>();

    k_layer<<<128, 512, SMEM_BYTES_MAX>>>(0, 0,  W0, b0);
    k_layer<<<128, 512, SMEM_BYTES_MAX>>>(1, T_, W1, b1);

    k_fc<<<B_, 96>>>(fcw, fcb, out);
    k_copy<<<(B_ * H_ + 255) / 256, 256>>>(out);
}

// round 17
// speedup vs baseline: 1.8039x; 1.4267x over previous
#include <cuda_runtime.h>
#include <cstdint>
#include <cuda_fp16.h>

#define B_    128
#define H_    1024
#define T_    256
#define D_    128
#define PRED_ 96
#define G4    4096

// Fragment-block layout for all fp16 activation tensors:
//   value (m, k) lives in block (kt = k>>4, mt = m>>4), 512 B per block.
//   rr = m&15, kk = k&15; lane = (rr&7)*4 + ((kk&7)>>1);
//   areg = ((kk>>3)<<1) | (rr>>3);  byte = lane*16 + areg*4 + (kk&1)*2
// A warp's LDG.128 at (block + lane*16) yields {a0,a1,a2,a3} for mma.m16n8k16.

// -------- scratch --------
__device__ alignas(256) __half g_Xseq16[(size_t)T_ * B_ * D_];   // frag blocks [t][kt(8)][mt(8)]
__device__ alignas(256) __half g_HS016[(size_t)T_ * B_ * H_];    // frag blocks [t][kt(64)][mt(8)]
__device__ alignas(256) __half g_h16A[B_ * H_];                  // frag blocks [kt(64)][mt(8)]
__device__ alignas(256) __half g_h16B[B_ * H_];
__device__ alignas(256) float  g_c[B_ * H_];                     // plain [m][j]
__device__ unsigned g_flag[B_];

__device__ __forceinline__ uint32_t f2h2(float a, float b) {
    __half2 h = __floats2half2_rn(a, b);
    return *(uint32_t*)&h;
}
__device__ __forceinline__ float sigf(float x) { return 1.f / (1.f + __expf(-x)); }
__device__ __forceinline__ uint4 ldcg4u(const void* p) {
    uint4 v;
    asm volatile("ld.global.cg.v4.u32 {%0,%1,%2,%3}, [%4];"
                 : "=r"(v.x), "=r"(v.y), "=r"(v.z), "=r"(v.w) : "l"(p));
    return v;
}
__device__ __forceinline__ void hmma(float* c, const uint4& a, uint32_t b0, uint32_t b1) {
    asm volatile(
        "mma.sync.aligned.m16n8k16.row.col.f32.f16.f16.f32 "
        "{%0,%1,%2,%3}, {%4,%5,%6,%7}, {%8,%9}, {%0,%1,%2,%3};"
        : "+f"(c[0]), "+f"(c[1]), "+f"(c[2]), "+f"(c[3])
        : "r"(a.x), "r"(a.y), "r"(a.z), "r"(a.w), "r"(b0), "r"(b1));
}

// -------- transpose x[b][d][t] -> Xseq16 fragment blocks --------
__global__ void k_transpose(const float* __restrict__ x) {
    __shared__ float tile[32][33];
    int b  = blockIdx.z;
    int d0 = blockIdx.x * 32, t0 = blockIdx.y * 32;
    int tx = threadIdx.x, ty = threadIdx.y;
#pragma unroll
    for (int i = 0; i < 32; i += 8)
        tile[ty + i][tx] = x[((size_t)b * D_ + d0 + ty + i) * T_ + t0 + tx];
    __syncthreads();
    int rr = b & 15;
#pragma unroll
    for (int i = 0; i < 32; i += 8) {
        int t = t0 + ty + i, d = d0 + tx;
        int kk = d & 15;
        int ln = (rr & 7) * 4 + ((kk & 7) >> 1);
        int ar = ((kk >> 3) << 1) | (rr >> 3);
        size_t off = (size_t)((t * 8 + (d >> 4)) * 8 + (b >> 4)) * 512
                   + ln * 16 + ar * 4 + (kk & 1) * 2;
        *(__half*)((uint8_t*)g_Xseq16 + off) = __float2half_rn(tile[tx][ty + i]);
    }
}

__global__ void k_zero() {
    int i = blockIdx.x * blockDim.x + threadIdx.x;
    if (i < B_ * H_) { g_h16A[i] = __float2half_rn(0.f); g_c[i] = 0.f; }
    if (i < B_) g_flag[i] = 0u;
}

// -------- persistent per-layer LSTM (fragment-direct, no smem staging) --------
// 128 CTAs (1/SM), 256 threads = 8 mma warps. CTA j: gate cols [8j,8j+8)x4.
// W fragments resident in smem per-lane-contiguous; A fragments via one
// coalesced LDG.128 per warp per k16-step directly from pre-swizzled global.
// No intra-step barriers at all.
__global__ void __launch_bounds__(256) k_layer(
    int layer, int tbase,
    const float* __restrict__ W, const float* __restrict__ bias)
{
    const int K1  = layer ? H_ : D_;
    const int nkt = (K1 + H_) >> 4;          // 72 or 128
    const int kt0 = K1 >> 4;                 // panel-0 kt count (64 or 8)

    extern __shared__ uint32_t wfrag[];      // [kt][sel(2)][lane][4 words]

    const int tid  = threadIdx.x;
    const int warp = tid >> 5, lane = tid & 31;
    const int r = lane >> 2, q = lane & 3;
    const int cta = blockIdx.x;
    const int j0 = cta * 8;

    // ---- build W fragment table (once) ----
    for (int idx = tid; idx < nkt * 256; idx += 256) {
        int kt = idx >> 8, rem = idx & 255;
        int sel = rem >> 7, rem2 = rem & 127;
        int ln = rem2 >> 2, w = rem2 & 3;
        int g = sel * 2 + (w >> 1), b01 = w & 1;
        int qq = ln & 3, rrw = ln >> 2;
        int k0 = kt * 16 + 2 * qq + b01 * 8;
        int col = g * H_ + j0 + rrw;
        wfrag[idx] = f2h2(W[(size_t)k0 * G4 + col], W[(size_t)(k0 + 1) * G4 + col]);
    }
    __syncthreads();

    // per-lane bias (cols j0+2q, j0+2q+1 per gate)
    float2 bia[4];
#pragma unroll
    for (int g = 0; g < 4; g++)
        bia[g] = *(const float2*)(bias + g * H_ + j0 + 2 * q);

    const int laneoff = lane * 16;
    const uint8_t* Xb = (const uint8_t*)g_Xseq16;
    const uint8_t* Hb = (const uint8_t*)g_HS016;

    for (int t = 0; t < T_; t++) {
        const int par = t & 1;
        const uint8_t* p0 = layer ? Hb + (size_t)t * (64 * 8 * 512)
                                  : Xb + (size_t)t * (8 * 8 * 512);
        const uint8_t* ph = (const uint8_t*)(par ? g_h16B : g_h16A);
        uint8_t* hnextB   = (uint8_t*)(par ? g_h16A : g_h16B);
        uint8_t* hsB      = layer ? nullptr
                                  : (uint8_t*)g_HS016 + (size_t)t * (64 * 8 * 512);

        auto aaddr = [&](int kt) -> const void* {
            const uint8_t* base; int ktl;
            if (kt < kt0) { base = p0; ktl = kt; }
            else          { base = ph; ktl = kt - kt0; }
            return base + (size_t)((ktl * 8 + warp) * 512) + laneoff;
        };

        float acc[4][4];
#pragma unroll
        for (int g = 0; g < 4; g++)
#pragma unroll
            for (int k = 0; k < 4; k++) acc[g][k] = 0.f;

        uint4 pa[4];
#pragma unroll
        for (int i = 0; i < 4; i++) pa[i] = ldcg4u(aaddr(i));

        for (int g0 = 0; g0 < nkt; g0 += 4) {
            uint4 ca[4];
#pragma unroll
            for (int i = 0; i < 4; i++) ca[i] = pa[i];
            if (g0 + 4 < nkt) {
#pragma unroll
                for (int i = 0; i < 4; i++) pa[i] = ldcg4u(aaddr(g0 + 4 + i));
            }
#pragma unroll
            for (int i = 0; i < 4; i++) {
                const uint4* wp = (const uint4*)(wfrag + (g0 + i) * 256);
                uint4 w01 = wp[lane];
                uint4 w23 = wp[lane + 32];
                hmma(acc[0], ca[i], w01.x, w01.y);
                hmma(acc[1], ca[i], w01.z, w01.w);
                hmma(acc[2], ca[i], w23.x, w23.y);
                hmma(acc[3], ca[i], w23.z, w23.w);
            }
        }

        // ---- epilogue (all in-register; this warp owns rows m_lo, m_lo+8) ----
        {
            int m_lo = warp * 16 + r;
            float* cl = g_c + (size_t)m_lo * H_ + j0 + 2 * q;
            float* chp = cl + 8 * H_;
            float2 c_lo = *(float2*)cl;
            float2 c_hi = *(float2*)chp;

            float hn[4];
            float cc[4] = {c_lo.x, c_lo.y, c_hi.x, c_hi.y};
#pragma unroll
            for (int e = 0; e < 4; e++) {
                float bb = (e & 1) ? 1.f : 0.f;   // col offset selector
                float zi = acc[0][e] + ((e & 1) ? bia[0].y : bia[0].x);
                float zf = acc[1][e] + ((e & 1) ? bia[1].y : bia[1].x);
                float zo = acc[2][e] + ((e & 1) ? bia[2].y : bia[2].x);
                float zg = acc[3][e] + ((e & 1) ? bia[3].y : bia[3].x);
                (void)bb;
                float i_ = sigf(zi), f_ = sigf(zf), o_ = sigf(zo);
                float g_ = tanhf(zg);
                float cn = f_ * cc[e] + i_ * g_;
                cc[e] = cn;
                hn[e] = o_ * tanhf(cn);
            }
            *(float2*)cl  = make_float2(cc[0], cc[1]);
            *(float2*)chp = make_float2(cc[2], cc[3]);

            // h fragment store: lane (r,q) -> same reader lane; aregs adjacent
            uint2 hv;
            hv.x = f2h2(hn[0], hn[1]);    // rows m_lo   (a0 or a2)
            hv.y = f2h2(hn[2], hn[3]);    // rows m_lo+8 (a1 or a3)
            size_t hblk = (size_t)((((cta >> 1) * 8) + warp) * 512)
                        + laneoff + (cta & 1) * 8;
            *(uint2*)(hnextB + hblk) = hv;
            if (hsB) *(uint2*)(hsB + hblk) = hv;
        }

        // ---- global step barrier via per-CTA flags ----
        __threadfence();
        __syncthreads();
        if (tid == 0)
            *(volatile unsigned*)&g_flag[cta] = (unsigned)(tbase + t + 1);
        if (t + 1 < T_) {
            unsigned target = (unsigned)(tbase + t + 1);
            if (tid < B_) {
                while (*(volatile unsigned*)&g_flag[tid] < target) __nanosleep(32);
                __threadfence();
            }
            __syncthreads();
        }
    }
}

// fragment-layout element access for final h
__device__ __forceinline__ float hval(const __half* h, int m, int k) {
    int rr = m & 15, kk = k & 15;
    int ln = (rr & 7) * 4 + ((kk & 7) >> 1);
    int ar = ((kk >> 3) << 1) | (rr >> 3);
    size_t off = (size_t)(((k >> 4) * 8) + (m >> 4)) * 512
               + ln * 16 + ar * 4 + (kk & 1) * 2;
    return __half2float(*(const __half*)((const uint8_t*)h + off));
}

// -------- final FC head --------
__global__ void k_fc(const float* __restrict__ fcw,
                     const float* __restrict__ fcb, float* __restrict__ out) {
    __shared__ float hsh[H_];
    int b = blockIdx.x;
    for (int i = threadIdx.x; i < H_; i += blockDim.x)
        hsh[i] = hval(g_h16A, b, i);
    __syncthreads();
    for (int p = threadIdx.x; p < PRED_; p += blockDim.x) {
        float s = fcb[p];
#pragma unroll 8
        for (int k = 0; k < H_; k++) s += hsh[k] * fcw[k * PRED_ + p];
        out[b * PRED_ + p] = tanhf(s);
    }
}

__global__ void k_copy(float* __restrict__ out) {
    int i = blockIdx.x * blockDim.x + threadIdx.x;
    if (i < B_ * H_) {
        int m = i >> 10, j = i & (H_ - 1);
        out[B_ * PRED_ + i]           = hval(g_h16A, m, j);
        out[B_ * PRED_ + B_ * H_ + i] = g_c[i];
    }
}

extern "C" void kernel_launch(void* const* d_in, const int* in_sizes, int n_in,
                              void* d_out, int out_size) {
    const float* x   = (const float*)d_in[0];
    const float* W0  = (const float*)d_in[1];
    const float* b0  = (const float*)d_in[2];
    const float* W1  = (const float*)d_in[3];
    const float* b1  = (const float*)d_in[4];
    const float* fcw = (const float*)d_in[5];
    const float* fcb = (const float*)d_in[6];
    float* out = (float*)d_out;

    const int smem1 = 128 * 256 * 4;   // 128 KB (layer-1 W fragment table)
    cudaFuncSetAttribute(k_layer, cudaFuncAttributeMaxDynamicSharedMemorySize, smem1);

    dim3 tg(D_ / 32, T_ / 32, B_);
    k_transpose<<<tg, dim3(32, 8)>>>(x);
    k_zero<<<(B_ * H_ + 255) / 256, 256>>>();

    k_layer<<<128, 256, 72 * 256 * 4>>>(0, 0,  W0, b0);
    k_layer<<<128, 256, smem1>>>(1, T_, W1, b1);

    k_fc<<<B_, 96>>>(fcw, fcb, out);
    k_copy<<<(B_ * H_ + 255) / 256, 256>>>(out);
}